// round 1
// baseline (speedup 1.0000x reference)
#include <cuda_runtime.h>
#include <math.h>

#define T_TOK 2048
#define HDIM  1024
#define FFND  4096
#define NE    8
#define NF2   8192   // 2*FFND
#define NPAIR (2*T_TOK)

// ---------------- scratch (static device globals; no allocation) ------------
__device__ int   d_count[NE];
__device__ int   d_list[NE * T_TOK];      // packed (token*2 + kslot)
__device__ float d_wgt[NPAIR];            // weight per (token,kslot)
__device__ float d_z[(size_t)NPAIR * NF2];    // 128 MiB: [pair, 8192] g|u
__device__ float d_actbuf[(size_t)NPAIR * FFND]; // 64 MiB: silu(g)*u
__device__ float d_y[(size_t)NPAIR * HDIM];   // 16 MiB: per-pair down-proj

// ---------------------------------------------------------------------------
__global__ void zero_counts_kernel() {
    if (threadIdx.x < NE) d_count[threadIdx.x] = 0;
}

// One warp per token: router logits, top-2 softmax weights, expert compaction.
__global__ void router_kernel(const float* __restrict__ x,
                              const float* __restrict__ gw,
                              float* __restrict__ rlogits) {
    int gwarp = (blockIdx.x * blockDim.x + threadIdx.x) >> 5;
    int lane  = threadIdx.x & 31;
    if (gwarp >= T_TOK) return;
    const float* xr = x + (size_t)gwarp * HDIM;

    float acc[NE];
#pragma unroll
    for (int e = 0; e < NE; e++) acc[e] = 0.f;
    for (int h = lane; h < HDIM; h += 32) {
        float xv = xr[h];
#pragma unroll
        for (int e = 0; e < NE; e++) acc[e] += xv * gw[e * HDIM + h];
    }
#pragma unroll
    for (int e = 0; e < NE; e++)
#pragma unroll
        for (int off = 16; off; off >>= 1)
            acc[e] += __shfl_xor_sync(0xffffffffu, acc[e], off);

    if (lane == 0) {
#pragma unroll
        for (int e = 0; e < NE; e++) rlogits[gwarp * NE + e] = acc[e];
        // top-2 of logits (== top-2 of softmax), lowest index wins ties
        int e0 = 0;
#pragma unroll
        for (int e = 1; e < NE; e++) if (acc[e] > acc[e0]) e0 = e;
        int e1 = (e0 == 0) ? 1 : 0;
#pragma unroll
        for (int e = 0; e < NE; e++)
            if (e != e0 && acc[e] > acc[e1]) e1 = e;
        // renormalized top-2 softmax weights
        float p1 = __expf(acc[e1] - acc[e0]);   // p0 = 1
        float inv = 1.0f / (1.0f + p1);
        float w0 = inv, w1 = p1 * inv;

        int pos0 = atomicAdd(&d_count[e0], 1);
        d_list[e0 * T_TOK + pos0] = gwarp * 2 + 0;
        d_wgt[gwarp * 2 + 0] = w0;
        int pos1 = atomicAdd(&d_count[e1], 1);
        d_list[e1 * T_TOK + pos1] = gwarp * 2 + 1;
        d_wgt[gwarp * 2 + 1] = w1;
    }
}

// ---------------- GEMM1: z[pair, n] = x[token] . w13[e][n]  (K=1024) --------
// 128x128x8 tile, 256 threads, 8x8 per thread. A rows gathered via pair list.
__global__ __launch_bounds__(256, 2)
void gemm1_kernel(const float* __restrict__ x, const float* __restrict__ w13) {
    int e   = blockIdx.z;
    int cnt = d_count[e];
    int m0  = blockIdx.x * 128;
    if (m0 >= cnt) return;
    int n0  = blockIdx.y * 128;

    __shared__ float As[8][128];
    __shared__ float Bs[8][128];
    __shared__ int   sPair[128];

    int tid = threadIdx.x;
    if (tid < 128) {
        int m = m0 + tid;
        sPair[tid] = d_list[e * T_TOK + (m < cnt ? m : m0)]; // clamp pad rows
    }
    __syncthreads();

    int aRow = tid >> 1;             // 0..127
    int aC   = (tid & 1) * 4;        // 0 or 4 (k offset)
    const float* aSrc = x  + (size_t)(sPair[aRow] >> 1) * HDIM + aC;
    const float* bSrc = w13 + ((size_t)e * NF2 + n0 + aRow) * HDIM + aC;

    float acc[8][8];
#pragma unroll
    for (int i = 0; i < 8; i++)
#pragma unroll
        for (int j = 0; j < 8; j++) acc[i][j] = 0.f;

    int tr = tid >> 4, tc = tid & 15;

    for (int k0 = 0; k0 < HDIM; k0 += 8) {
        float4 av = *(const float4*)(aSrc + k0);
        float4 bv = *(const float4*)(bSrc + k0);
        As[aC + 0][aRow] = av.x; As[aC + 1][aRow] = av.y;
        As[aC + 2][aRow] = av.z; As[aC + 3][aRow] = av.w;
        Bs[aC + 0][aRow] = bv.x; Bs[aC + 1][aRow] = bv.y;
        Bs[aC + 2][aRow] = bv.z; Bs[aC + 3][aRow] = bv.w;
        __syncthreads();
#pragma unroll
        for (int k = 0; k < 8; k++) {
            float a[8], b[8];
            *(float4*)(a)     = *(const float4*)&As[k][tr * 8];
            *(float4*)(a + 4) = *(const float4*)&As[k][tr * 8 + 4];
            *(float4*)(b)     = *(const float4*)&Bs[k][tc * 8];
            *(float4*)(b + 4) = *(const float4*)&Bs[k][tc * 8 + 4];
#pragma unroll
            for (int i = 0; i < 8; i++)
#pragma unroll
                for (int j = 0; j < 8; j++) acc[i][j] += a[i] * b[j];
        }
        __syncthreads();
    }

#pragma unroll
    for (int i = 0; i < 8; i++) {
        int mloc = tr * 8 + i;
        if (m0 + mloc < cnt) {
            int p = sPair[mloc];
            float* dst = d_z + (size_t)p * NF2 + n0 + tc * 8;
            *(float4*)(dst)     = *(float4*)&acc[i][0];
            *(float4*)(dst + 4) = *(float4*)&acc[i][4];
        }
    }
}

// ---------------- act: silu(g) * u ------------------------------------------
__global__ void act_kernel() {
    size_t total = (size_t)NPAIR * FFND;
    for (size_t i = (size_t)blockIdx.x * blockDim.x + threadIdx.x;
         i < total; i += (size_t)gridDim.x * blockDim.x) {
        size_t p = i / FFND;
        size_t f = i - p * FFND;
        float g = d_z[p * NF2 + f];
        float u = d_z[p * NF2 + FFND + f];
        d_actbuf[i] = (g / (1.0f + __expf(-g))) * u;
    }
}

// ---------------- GEMM2: y[pair, n] = act[pair] . w2[e][n]  (K=4096) --------
__global__ __launch_bounds__(256, 2)
void gemm2_kernel(const float* __restrict__ w2) {
    int e   = blockIdx.z;
    int cnt = d_count[e];
    int m0  = blockIdx.x * 128;
    if (m0 >= cnt) return;
    int n0  = blockIdx.y * 128;   // over HDIM (8 tiles)

    __shared__ float As[8][128];
    __shared__ float Bs[8][128];
    __shared__ int   sPair[128];

    int tid = threadIdx.x;
    if (tid < 128) {
        int m = m0 + tid;
        sPair[tid] = d_list[e * T_TOK + (m < cnt ? m : m0)];
    }
    __syncthreads();

    int aRow = tid >> 1;
    int aC   = (tid & 1) * 4;
    const float* aSrc = d_actbuf + (size_t)sPair[aRow] * FFND + aC;
    const float* bSrc = w2 + ((size_t)e * HDIM + n0 + aRow) * FFND + aC;

    float acc[8][8];
#pragma unroll
    for (int i = 0; i < 8; i++)
#pragma unroll
        for (int j = 0; j < 8; j++) acc[i][j] = 0.f;

    int tr = tid >> 4, tc = tid & 15;

    for (int k0 = 0; k0 < FFND; k0 += 8) {
        float4 av = *(const float4*)(aSrc + k0);
        float4 bv = *(const float4*)(bSrc + k0);
        As[aC + 0][aRow] = av.x; As[aC + 1][aRow] = av.y;
        As[aC + 2][aRow] = av.z; As[aC + 3][aRow] = av.w;
        Bs[aC + 0][aRow] = bv.x; Bs[aC + 1][aRow] = bv.y;
        Bs[aC + 2][aRow] = bv.z; Bs[aC + 3][aRow] = bv.w;
        __syncthreads();
#pragma unroll
        for (int k = 0; k < 8; k++) {
            float a[8], b[8];
            *(float4*)(a)     = *(const float4*)&As[k][tr * 8];
            *(float4*)(a + 4) = *(const float4*)&As[k][tr * 8 + 4];
            *(float4*)(b)     = *(const float4*)&Bs[k][tc * 8];
            *(float4*)(b + 4) = *(const float4*)&Bs[k][tc * 8 + 4];
#pragma unroll
            for (int i = 0; i < 8; i++)
#pragma unroll
                for (int j = 0; j < 8; j++) acc[i][j] += a[i] * b[j];
        }
        __syncthreads();
    }

#pragma unroll
    for (int i = 0; i < 8; i++) {
        int mloc = tr * 8 + i;
        if (m0 + mloc < cnt) {
            int p = sPair[mloc];
            float* dst = d_y + (size_t)p * HDIM + n0 + tc * 8;
            *(float4*)(dst)     = *(float4*)&acc[i][0];
            *(float4*)(dst + 4) = *(float4*)&acc[i][4];
        }
    }
}

// ---------------- combine: out[t] = w0*y[2t] + w1*y[2t+1] -------------------
__global__ void combine_kernel(float* __restrict__ out) {
    int i4 = blockIdx.x * blockDim.x + threadIdx.x;   // over T*H/4
    int t  = i4 / (HDIM / 4);
    int h4 = i4 - t * (HDIM / 4);
    if (t >= T_TOK) return;
    float w0 = d_wgt[2 * t], w1 = d_wgt[2 * t + 1];
    const float4* y0 = (const float4*)(d_y + (size_t)(2 * t) * HDIM) + h4;
    const float4* y1 = (const float4*)(d_y + (size_t)(2 * t + 1) * HDIM) + h4;
    float4 a = *y0, b = *y1, r;
    r.x = w0 * a.x + w1 * b.x;
    r.y = w0 * a.y + w1 * b.y;
    r.z = w0 * a.z + w1 * b.z;
    r.w = w0 * a.w + w1 * b.w;
    ((float4*)(out + (size_t)t * HDIM))[h4] = r;
}

// ---------------------------------------------------------------------------
extern "C" void kernel_launch(void* const* d_in, const int* in_sizes, int n_in,
                              void* d_out, int out_size) {
    const float* x   = (const float*)d_in[0];  // [2048, 1024]
    const float* gw  = (const float*)d_in[1];  // [8, 1024]
    const float* w13 = (const float*)d_in[2];  // [8, 8192, 1024]
    const float* w2  = (const float*)d_in[3];  // [8, 1024, 4096]
    float* out = (float*)d_out;                // [2048*1024] then [2048*8]
    float* rlogits = out + (size_t)T_TOK * HDIM;

    zero_counts_kernel<<<1, 32>>>();
    router_kernel<<<T_TOK / 8, 256>>>(x, gw, rlogits);

    dim3 g1(T_TOK / 128, NF2 / 128, NE);      // (16, 64, 8)
    gemm1_kernel<<<g1, 256>>>(x, w13);

    act_kernel<<<4096, 256>>>();

    dim3 g2(T_TOK / 128, HDIM / 128, NE);     // (16, 8, 8)
    gemm2_kernel<<<g2, 256>>>(w2);

    combine_kernel<<<(T_TOK * HDIM / 4 + 255) / 256, 256>>>(out);
}